// round 4
// baseline (speedup 1.0000x reference)
#include <cuda_runtime.h>
#include <cuda_bf16.h>
#include <math.h>
#include <stdint.h>

// ---------------- problem constants ----------------------------------------
#define BB   2
#define SS   1024
#define DD   1024
#define HH   16
#define DKK  64
#define FF   4096
#define LL   4
#define VV   32000
#define MM   (BB*SS)
#define LNEPS 1e-5f

// ---------------- bf16 weight pool offsets (elements) ----------------------
#define D2      (DD*DD)
#define SZ_QKV  (LL*3*D2)
#define SZ_D2   (LL*D2)
#define SZ_FD   (LL*FF*DD)
#define SZ_HW   (VV*DD)
#define OFF_QKV 0
#define OFF_WO  (SZ_QKV)
#define OFF_W1  (OFF_WO + SZ_D2)
#define OFF_W2  (OFF_W1 + SZ_FD)
#define OFF_HW  (OFF_W2 + SZ_FD)
#define WTOT    (OFF_HW + SZ_HW)

// ---------------- device scratch (no allocation allowed) -------------------
__device__ float g_x   [MM*DD];
__device__ float g_qkv [MM*3*DD];
__device__ float g_tmp [MM*DD];
__device__ float g_sc  [(size_t)BB*HH*SS*SS];
__device__ __nv_bfloat16 g_whi[WTOT];
__device__ __nv_bfloat16 g_wlo[WTOT];
__device__ __nv_bfloat16 g_xhi[MM*DD];
__device__ __nv_bfloat16 g_xlo[MM*DD];
__device__ __nv_bfloat16 g_ohi[MM*DD];
__device__ __nv_bfloat16 g_olo[MM*DD];
__device__ __nv_bfloat16 g_fhi[MM*FF];
__device__ __nv_bfloat16 g_flo[MM*FF];

// ---------------- helpers ---------------------------------------------------
__device__ __forceinline__ uint32_t smem_u32(const void* p) {
    uint32_t a;
    asm("{ .reg .u64 t; cvta.to.shared.u64 t, %1; cvt.u32.u64 %0, t; }"
        : "=r"(a) : "l"(p));
    return a;
}
#define LDSM_X4(r0, r1, r2, r3, addr) \
    asm volatile("ldmatrix.sync.aligned.m8n8.x4.shared.b16 {%0,%1,%2,%3}, [%4];" \
                 : "=r"(r0), "=r"(r1), "=r"(r2), "=r"(r3) : "r"(addr))
#define MMA_BF16(c0, c1, c2, c3, a0, a1, a2, a3, b0, b1) \
    asm volatile("mma.sync.aligned.m16n8k16.row.col.f32.bf16.bf16.f32 " \
                 "{%0,%1,%2,%3}, {%4,%5,%6,%7}, {%8,%9}, {%0,%1,%2,%3};" \
                 : "+f"(c0), "+f"(c1), "+f"(c2), "+f"(c3) \
                 : "r"(a0), "r"(a1), "r"(a2), "r"(a3), "r"(b0), "r"(b1))

__device__ __forceinline__ void split1(float v, __nv_bfloat16& h, __nv_bfloat16& l) {
    h = __float2bfloat16(v);
    l = __float2bfloat16(v - __bfloat162float(h));
}

// ---------------- split fp32 -> (hi, lo) bf16 (weights only) ----------------
__global__ void split_bf16(const float* __restrict__ x,
                           __nv_bfloat16* __restrict__ hi,
                           __nv_bfloat16* __restrict__ lo, int n)
{
    int i = (blockIdx.x * 256 + threadIdx.x) * 4;
    if (i >= n) return;
    float4 v = *(const float4*)(x + i);
    __nv_bfloat16 h0, h1, h2, h3, l0, l1, l2, l3;
    split1(v.x, h0, l0); split1(v.y, h1, l1);
    split1(v.z, h2, l2); split1(v.w, h3, l3);
    hi[i + 0] = h0; hi[i + 1] = h1; hi[i + 2] = h2; hi[i + 3] = h3;
    lo[i + 0] = l0; lo[i + 1] = l1; lo[i + 2] = l2; lo[i + 3] = l3;
}

// ---------------- HMMA GEMM: C[M,N] = A[M,K] @ B[N,K]^T ---------------------
// 3-pass bf16 split, fp32 accum. CTA 64x128, 8 warps of 32x32, BK=32,
// double-buffered smem with register staging. Epilogue: bias (up to 3 segments
// of 1024 for fused QKV), optional relu, optional fp32 out, optional hi/lo out.
#define SAST 40

__global__ __launch_bounds__(256, 2)
void gemm_mma(const __nv_bfloat16* __restrict__ Ahi, const __nv_bfloat16* __restrict__ Alo,
              const __nv_bfloat16* __restrict__ Bhi, const __nv_bfloat16* __restrict__ Blo,
              const float* __restrict__ bias0, const float* __restrict__ bias1,
              const float* __restrict__ bias2,
              float* __restrict__ C32,
              __nv_bfloat16* __restrict__ Chi, __nv_bfloat16* __restrict__ Clo,
              int M, int N, int K, int relu)
{
    __shared__ __nv_bfloat16 sA[2][64 * SAST];
    __shared__ __nv_bfloat16 sB[2][128 * SAST];

    int tid  = threadIdx.x;
    int lane = tid & 31;
    int wid  = tid >> 5;
    int wm   = (wid & 1) * 32;
    int wn   = (wid >> 1) * 32;
    int m0   = blockIdx.y * 64;
    int n0   = blockIdx.x * 128;

    float c[2][4][4];
#pragma unroll
    for (int i = 0; i < 2; i++)
#pragma unroll
        for (int j = 0; j < 4; j++)
#pragma unroll
            for (int r = 0; r < 4; r++) c[i][j][r] = 0.f;

    const int KC = K >> 5;
    const int T  = 3 * KC;

    int arow = tid >> 2, aseg = (tid & 3) * 8;   // A: 64 rows x 4 segs
    uint4 ra, rb0, rb1;

    // prologue: chunk 0 (hi*hi, k0=0)
    ra  = *(const uint4*)(Ahi + (size_t)(m0 + arow) * K + aseg);
    rb0 = *(const uint4*)(Bhi + (size_t)(n0 + arow) * K + aseg);
    rb1 = *(const uint4*)(Bhi + (size_t)(n0 + arow + 64) * K + aseg);
    *(uint4*)&sA[0][arow * SAST + aseg]        = ra;
    *(uint4*)&sB[0][arow * SAST + aseg]        = rb0;
    *(uint4*)&sB[0][(arow + 64) * SAST + aseg] = rb1;
    __syncthreads();

    for (int cc = 0; cc < T; ++cc) {
        int p = cc & 1;

        if (cc + 1 < T) {
            int nxt = cc + 1;
            int seg = nxt / KC;
            int k0  = (nxt - seg * KC) << 5;
            const __nv_bfloat16* As = (seg == 2) ? Alo : Ahi;
            const __nv_bfloat16* Bs = (seg == 1) ? Blo : Bhi;
            ra  = *(const uint4*)(As + (size_t)(m0 + arow) * K + k0 + aseg);
            rb0 = *(const uint4*)(Bs + (size_t)(n0 + arow) * K + k0 + aseg);
            rb1 = *(const uint4*)(Bs + (size_t)(n0 + arow + 64) * K + k0 + aseg);
        }

        uint32_t baseA = smem_u32(&sA[p][0]);
        uint32_t baseB = smem_u32(&sB[p][0]);
#pragma unroll
        for (int kk = 0; kk < 32; kk += 16) {
            uint32_t a[2][4], bf[2][4];
#pragma unroll
            for (int ma = 0; ma < 2; ma++) {
                uint32_t addr = baseA +
                    (((wm + ma * 16 + (lane & 15)) * SAST) + kk + ((lane >> 4) * 8)) * 2;
                LDSM_X4(a[ma][0], a[ma][1], a[ma][2], a[ma][3], addr);
            }
#pragma unroll
            for (int nb2 = 0; nb2 < 2; nb2++) {
                uint32_t addr = baseB +
                    (((wn + nb2 * 16 + (lane & 15)) * SAST) + kk + ((lane >> 4) * 8)) * 2;
                LDSM_X4(bf[nb2][0], bf[nb2][1], bf[nb2][2], bf[nb2][3], addr);
            }
#pragma unroll
            for (int ma = 0; ma < 2; ma++)
#pragma unroll
                for (int nb = 0; nb < 4; nb++) {
                    int n2 = nb >> 1, h = nb & 1;
                    MMA_BF16(c[ma][nb][0], c[ma][nb][1], c[ma][nb][2], c[ma][nb][3],
                             a[ma][0], a[ma][1], a[ma][2], a[ma][3],
                             bf[n2][h], bf[n2][h + 2]);
                }
        }

        if (cc + 1 < T) {
            int q = p ^ 1;
            *(uint4*)&sA[q][arow * SAST + aseg]        = ra;
            *(uint4*)&sB[q][arow * SAST + aseg]        = rb0;
            *(uint4*)&sB[q][(arow + 64) * SAST + aseg] = rb1;
        }
        __syncthreads();
    }

    // ---- epilogue
#pragma unroll
    for (int ma = 0; ma < 2; ma++) {
        int mrow = m0 + wm + ma * 16 + (lane >> 2);
#pragma unroll
        for (int nb = 0; nb < 4; nb++) {
            int ncol = n0 + wn + nb * 8 + (lane & 3) * 2;
            float b0 = 0.f, b1 = 0.f;
            if (bias0) {
                const float* bb = bias0;
                int off = 0;
                if (bias1 && ncol >= 1024) {
                    if (ncol < 2048) { bb = bias1; off = 1024; }
                    else             { bb = bias2; off = 2048; }
                }
                b0 = bb[ncol - off]; b1 = bb[ncol + 1 - off];
            }
            float v00 = c[ma][nb][0] + b0, v01 = c[ma][nb][1] + b1;
            float v10 = c[ma][nb][2] + b0, v11 = c[ma][nb][3] + b1;
            if (relu) {
                v00 = fmaxf(v00, 0.f); v01 = fmaxf(v01, 0.f);
                v10 = fmaxf(v10, 0.f); v11 = fmaxf(v11, 0.f);
            }
            size_t i0 = (size_t)mrow * N + ncol;
            size_t i1 = (size_t)(mrow + 8) * N + ncol;
            if (C32) {
                *(float2*)(C32 + i0) = make_float2(v00, v01);
                *(float2*)(C32 + i1) = make_float2(v10, v11);
            }
            if (Chi) {
                __nv_bfloat16 h00, h01, h10, h11, l00, l01, l10, l11;
                split1(v00, h00, l00); split1(v01, h01, l01);
                split1(v10, h10, l10); split1(v11, h11, l11);
                *(__nv_bfloat162*)(Chi + i0) = __nv_bfloat162(h00, h01);
                *(__nv_bfloat162*)(Chi + i1) = __nv_bfloat162(h10, h11);
                *(__nv_bfloat162*)(Clo + i0) = __nv_bfloat162(l00, l01);
                *(__nv_bfloat162*)(Clo + i1) = __nv_bfloat162(l10, l11);
            }
        }
    }
}

// ---------------- embedding + PE (emits x + hi/lo) --------------------------
__global__ void embed_pe_kernel(const int* __restrict__ ids,
                                const float* __restrict__ emb,
                                float* __restrict__ x,
                                __nv_bfloat16* __restrict__ xhi,
                                __nv_bfloat16* __restrict__ xlo)
{
    int idx = blockIdx.x * 256 + threadIdx.x;
    int m = idx >> 10;
    int d = idx & 1023;
    int s = m & (SS - 1);
    int tok = ids[m];
    int twohalf = (d >> 1) << 1;
    float div = __expf(-(float)twohalf * (9.210340371976184f / (float)DD));
    float ang = (float)s * div;
    float pe  = (d & 1) ? cosf(ang) : sinf(ang);
    float v = emb[(size_t)tok * DD + d] * 32.0f + pe;
    x[idx] = v;
    __nv_bfloat16 h, l; split1(v, h, l);
    xhi[idx] = h; xlo[idx] = l;
}

// ---------------- attention scores (fp32 SIMT, causal, skip masked) ---------
__global__ __launch_bounds__(256)
void attn_scores(const float* __restrict__ qkv, float* __restrict__ sc)
{
    int bh = blockIdx.z;
    int b = bh >> 4, h = bh & 15;
    int i0 = blockIdx.y * 128, j0 = blockIdx.x * 128;
    if (j0 > i0) return;                       // fully masked tile: skip entirely
    float* out = sc + (size_t)bh * SS * SS;
    int tid = threadIdx.x;

    const float* qb = qkv + (size_t)b * SS * (3 * DD) + h * DKK;
    const float* kb = qb + DD;
    __shared__ float Qs[8][128];
    __shared__ float Ks[8][128];
    int lrow = tid >> 1, lcol = (tid & 1) << 2;
    int ty = tid >> 4, tx = tid & 15;
    float acc[8][8];
#pragma unroll
    for (int i = 0; i < 8; i++)
#pragma unroll
        for (int j = 0; j < 8; j++) acc[i][j] = 0.f;
    for (int k0 = 0; k0 < DKK; k0 += 8) {
        float4 av = *(const float4*)(qb + (size_t)(i0 + lrow) * (3 * DD) + k0 + lcol);
        float4 bv = *(const float4*)(kb + (size_t)(j0 + lrow) * (3 * DD) + k0 + lcol);
        __syncthreads();
        Qs[lcol + 0][lrow] = av.x; Qs[lcol + 1][lrow] = av.y;
        Qs[lcol + 2][lrow] = av.z; Qs[lcol + 3][lrow] = av.w;
        Ks[lcol + 0][lrow] = bv.x; Ks[lcol + 1][lrow] = bv.y;
        Ks[lcol + 2][lrow] = bv.z; Ks[lcol + 3][lrow] = bv.w;
        __syncthreads();
#pragma unroll
        for (int kk = 0; kk < 8; kk++) {
            float a[8], bb_[8];
#pragma unroll
            for (int i = 0; i < 8; i++) a[i]   = Qs[kk][ty * 8 + i];
#pragma unroll
            for (int j = 0; j < 8; j++) bb_[j] = Ks[kk][tx * 8 + j];
#pragma unroll
            for (int i = 0; i < 8; i++)
#pragma unroll
                for (int j = 0; j < 8; j++) acc[i][j] += a[i] * bb_[j];
        }
    }
    const float scale = 0.125f;
#pragma unroll
    for (int i = 0; i < 8; i++) {
        int row = i0 + ty * 8 + i;
#pragma unroll
        for (int j = 0; j < 8; j++) {
            int col = j0 + tx * 8 + j;
            float v = acc[i][j] * scale;
            if (col > row) v = -1e9f;
            out[(size_t)row * SS + col] = v;
        }
    }
}

// ---------------- causal row softmax (processes only valid prefix) ----------
__global__ __launch_bounds__(256)
void softmax_rows(float* __restrict__ sc)
{
    int blk = blockIdx.x;
    int i  = blk & (SS - 1);
    int bh = blk >> 10;
    float* p = sc + (size_t)bh * SS * SS + (size_t)i * SS;
    int u = (i >> 8) + 1;                      // segments of 256
    int t = threadIdx.x, lane = t & 31, w = t >> 5;
    __shared__ float red[8];

    float v[4];
    float m = -3.0e38f;
    for (int s = 0; s < u; s++) {
        int j = t + s * 256;
        float val = (j <= i) ? p[j] : -1e9f;
        v[s] = val;
        m = fmaxf(m, val);
    }
#pragma unroll
    for (int o = 16; o > 0; o >>= 1) m = fmaxf(m, __shfl_xor_sync(~0u, m, o));
    if (lane == 0) red[w] = m;
    __syncthreads();
    m = red[0];
#pragma unroll
    for (int q = 1; q < 8; q++) m = fmaxf(m, red[q]);
    __syncthreads();

    float sum = 0.f;
    for (int s = 0; s < u; s++) { v[s] = __expf(v[s] - m); sum += v[s]; }
#pragma unroll
    for (int o = 16; o > 0; o >>= 1) sum += __shfl_xor_sync(~0u, sum, o);
    if (lane == 0) red[w] = sum;
    __syncthreads();
    sum = red[0];
#pragma unroll
    for (int q = 1; q < 8; q++) sum += red[q];

    float inv = 1.f / sum;
    for (int s = 0; s < u; s++) p[t + s * 256] = v[s] * inv;
}

// ---------------- o = attn @ v (emits hi/lo bf16) ----------------------------
__global__ __launch_bounds__(256)
void attn_av(const float* __restrict__ sc, const float* __restrict__ qkv,
             __nv_bfloat16* __restrict__ ohi, __nv_bfloat16* __restrict__ olo)
{
    int bh = blockIdx.y;
    int b = bh >> 4, h = bh & 15;
    int i0 = blockIdx.x * 64;
    const float* A  = sc  + (size_t)bh * SS * SS;
    const float* vb = qkv + (size_t)b * SS * (3 * DD) + 2 * DD + h * DKK;
    __shared__ float As[16][64];
    __shared__ float Vs[16][64];
    int t  = threadIdx.x;
    int ar = t >> 2,  ac = (t & 3) << 2;
    int vr = t >> 4,  vc = (t & 15) << 2;
    int ty = t >> 4,  tx = t & 15;
    float acc[4][4];
#pragma unroll
    for (int i = 0; i < 4; i++)
#pragma unroll
        for (int j = 0; j < 4; j++) acc[i][j] = 0.f;
    int kmax = i0 + 64;
    for (int k0 = 0; k0 < kmax; k0 += 16) {
        float4 av = *(const float4*)(A  + (size_t)(i0 + ar) * SS + k0 + ac);
        float4 vv = *(const float4*)(vb + (size_t)(k0 + vr) * (3 * DD) + vc);
        __syncthreads();
        As[ac + 0][ar] = av.x; As[ac + 1][ar] = av.y;
        As[ac + 2][ar] = av.z; As[ac + 3][ar] = av.w;
        *(float4*)&Vs[vr][vc] = vv;
        __syncthreads();
#pragma unroll
        for (int kk = 0; kk < 16; kk++) {
            float a[4], bv_[4];
#pragma unroll
            for (int i = 0; i < 4; i++) a[i]   = As[kk][ty * 4 + i];
#pragma unroll
            for (int j = 0; j < 4; j++) bv_[j] = Vs[kk][tx * 4 + j];
#pragma unroll
            for (int i = 0; i < 4; i++)
#pragma unroll
                for (int j = 0; j < 4; j++) acc[i][j] += a[i] * bv_[j];
        }
    }
#pragma unroll
    for (int i = 0; i < 4; i++) {
        size_t row = (size_t)(b * SS + i0 + ty * 4 + i) * DD + h * DKK + tx * 4;
#pragma unroll
        for (int j = 0; j < 4; j += 2) {
            __nv_bfloat16 h0, h1, l0, l1;
            split1(acc[i][j],     h0, l0);
            split1(acc[i][j + 1], h1, l1);
            *(__nv_bfloat162*)(ohi + row + j) = __nv_bfloat162(h0, h1);
            *(__nv_bfloat162*)(olo + row + j) = __nv_bfloat162(l0, l1);
        }
    }
}

// ---------------- fused residual + LayerNorm (emits x + hi/lo) --------------
__global__ __launch_bounds__(256)
void add_ln(const float* __restrict__ x, const float* __restrict__ y,
            const float* __restrict__ g, const float* __restrict__ bta,
            float* __restrict__ out,
            __nv_bfloat16* __restrict__ ohi, __nv_bfloat16* __restrict__ olo)
{
    __shared__ float red[256];
    int row = blockIdx.x;
    int t = threadIdx.x;
    const float* xr = x + (size_t)row * DD;
    float v[4];
    float s = 0.f;
#pragma unroll
    for (int u = 0; u < 4; u++) {
        int idx = t + u * 256;
        float vv = xr[idx];
        if (y) vv += y[(size_t)row * DD + idx];
        v[u] = vv;
        s += vv;
    }
    red[t] = s; __syncthreads();
    for (int w = 128; w > 0; w >>= 1) {
        if (t < w) red[t] += red[t + w];
        __syncthreads();
    }
    float mean = red[0] * (1.f / DD); __syncthreads();
    float s2 = 0.f;
#pragma unroll
    for (int u = 0; u < 4; u++) { float d = v[u] - mean; s2 += d * d; }
    red[t] = s2; __syncthreads();
    for (int w = 128; w > 0; w >>= 1) {
        if (t < w) red[t] += red[t + w];
        __syncthreads();
    }
    float rstd = rsqrtf(red[0] * (1.f / DD) + LNEPS);
    float* orow = out + (size_t)row * DD;
#pragma unroll
    for (int u = 0; u < 4; u++) {
        int idx = t + u * 256;
        float val = (v[u] - mean) * rstd * g[idx] + bta[idx];
        orow[idx] = val;
        __nv_bfloat16 h, l; split1(val, h, l);
        ohi[(size_t)row * DD + idx] = h;
        olo[(size_t)row * DD + idx] = l;
    }
}

// ---------------- host orchestration ----------------------------------------
extern "C" void kernel_launch(void* const* d_in, const int* in_sizes, int n_in,
                              void* d_out, int out_size)
{
    (void)in_sizes; (void)n_in; (void)out_size;
    const int*   ids    = (const int*)  d_in[0];
    const float* embedw = (const float*)d_in[1];
    const float* Wq     = (const float*)d_in[2];
    const float* bq     = (const float*)d_in[3];
    const float* Wk     = (const float*)d_in[4];
    const float* bk     = (const float*)d_in[5];
    const float* Wv     = (const float*)d_in[6];
    const float* bv     = (const float*)d_in[7];
    const float* Wo     = (const float*)d_in[8];
    const float* bo     = (const float*)d_in[9];
    const float* ln1_g  = (const float*)d_in[10];
    const float* ln1_b  = (const float*)d_in[11];
    const float* W1     = (const float*)d_in[12];
    const float* b1     = (const float*)d_in[13];
    const float* W2     = (const float*)d_in[14];
    const float* b2     = (const float*)d_in[15];
    const float* ln2_g  = (const float*)d_in[16];
    const float* ln2_b  = (const float*)d_in[17];
    const float* lnf_g  = (const float*)d_in[18];
    const float* lnf_b  = (const float*)d_in[19];
    const float* head_w = (const float*)d_in[20];
    float* out = (float*)d_out;

    float *x, *qkv, *tmp, *sc;
    __nv_bfloat16 *whi, *wlo, *xhi, *xlo, *ohi, *olo, *fhi, *flo;
    cudaGetSymbolAddress((void**)&x,   g_x);
    cudaGetSymbolAddress((void**)&qkv, g_qkv);
    cudaGetSymbolAddress((void**)&tmp, g_tmp);
    cudaGetSymbolAddress((void**)&sc,  g_sc);
    cudaGetSymbolAddress((void**)&whi, g_whi);
    cudaGetSymbolAddress((void**)&wlo, g_wlo);
    cudaGetSymbolAddress((void**)&xhi, g_xhi);
    cudaGetSymbolAddress((void**)&xlo, g_xlo);
    cudaGetSymbolAddress((void**)&ohi, g_ohi);
    cudaGetSymbolAddress((void**)&olo, g_olo);
    cudaGetSymbolAddress((void**)&fhi, g_fhi);
    cudaGetSymbolAddress((void**)&flo, g_flo);

    auto split = [&](const float* s, __nv_bfloat16* h, __nv_bfloat16* l, int n) {
        split_bf16<<<n / 1024, 256>>>(s, h, l, n);
    };
    auto gemm = [&](const __nv_bfloat16* aH, const __nv_bfloat16* aL,
                    const __nv_bfloat16* bH, const __nv_bfloat16* bL,
                    const float* b0, const float* b1_, const float* b2_,
                    float* C32, __nv_bfloat16* Chi, __nv_bfloat16* Clo,
                    int M, int N, int K, int relu) {
        gemm_mma<<<dim3(N / 128, M / 64), 256>>>(aH, aL, bH, bL, b0, b1_, b2_,
                                                 C32, Chi, Clo, M, N, K, relu);
    };

    // weight split: QKV interleaved per layer, rest contiguous
    for (int l = 0; l < LL; l++) {
        split(Wq + (size_t)l * D2, whi + OFF_QKV + (size_t)(3 * l + 0) * D2,
              wlo + OFF_QKV + (size_t)(3 * l + 0) * D2, D2);
        split(Wk + (size_t)l * D2, whi + OFF_QKV + (size_t)(3 * l + 1) * D2,
              wlo + OFF_QKV + (size_t)(3 * l + 1) * D2, D2);
        split(Wv + (size_t)l * D2, whi + OFF_QKV + (size_t)(3 * l + 2) * D2,
              wlo + OFF_QKV + (size_t)(3 * l + 2) * D2, D2);
    }
    split(Wo,     whi + OFF_WO, wlo + OFF_WO, SZ_D2);
    split(W1,     whi + OFF_W1, wlo + OFF_W1, SZ_FD);
    split(W2,     whi + OFF_W2, wlo + OFF_W2, SZ_FD);
    split(head_w, whi + OFF_HW, wlo + OFF_HW, SZ_HW);

    embed_pe_kernel<<<(MM * DD) / 256, 256>>>(ids, embedw, x, xhi, xlo);

    dim3 gSc(SS / 128, SS / 128, BB * HH);
    dim3 gAv(SS / 64, BB * HH);

    for (int l = 0; l < LL; l++) {
        size_t q3 = OFF_QKV + (size_t)l * 3 * D2;
        size_t od = OFF_WO + (size_t)l * D2;
        size_t f1 = OFF_W1 + (size_t)l * FF * DD;
        size_t f2 = OFF_W2 + (size_t)l * FF * DD;

        // fused QKV: [M, 3072]
        gemm(xhi, xlo, whi + q3, wlo + q3, bq + l * DD, bk + l * DD, bv + l * DD,
             qkv, nullptr, nullptr, MM, 3 * DD, DD, 0);

        attn_scores <<<gSc, 256>>>(qkv, sc);
        softmax_rows<<<BB * HH * SS, 256>>>(sc);
        attn_av     <<<gAv, 256>>>(sc, qkv, ohi, olo);

        gemm(ohi, olo, whi + od, wlo + od, bo + l * DD, nullptr, nullptr,
             tmp, nullptr, nullptr, MM, DD, DD, 0);
        add_ln<<<MM, 256>>>(x, tmp, ln1_g + l * DD, ln1_b + l * DD, x, xhi, xlo);

        gemm(xhi, xlo, whi + f1, wlo + f1, b1 + l * FF, nullptr, nullptr,
             nullptr, fhi, flo, MM, FF, DD, 1);
        gemm(fhi, flo, whi + f2, wlo + f2, b2 + l * DD, nullptr, nullptr,
             tmp, nullptr, nullptr, MM, DD, FF, 0);
        add_ln<<<MM, 256>>>(x, tmp, ln2_g + l * DD, ln2_b + l * DD, x, xhi, xlo);
    }

    add_ln<<<MM, 256>>>(x, (const float*)nullptr, lnf_g, lnf_b, x, xhi, xlo);
    gemm(xhi, xlo, whi + OFF_HW, wlo + OFF_HW, nullptr, nullptr, nullptr,
         out, nullptr, nullptr, MM, VV, DD, 0);
}

// round 5
// speedup vs baseline: 1.7650x; 1.7650x over previous
#include <cuda_runtime.h>
#include <cuda_bf16.h>
#include <math.h>
#include <stdint.h>

// ---------------- problem constants ----------------------------------------
#define BB   2
#define SS   1024
#define DD   1024
#define HH   16
#define DKK  64
#define FF   4096
#define LL   4
#define VV   32000
#define MM   (BB*SS)
#define LNEPS 1e-5f

// ---------------- bf16 weight pool offsets (elements) ----------------------
#define D2      (DD*DD)
#define SZ_QKV  (LL*3*D2)
#define SZ_D2   (LL*D2)
#define SZ_FD   (LL*FF*DD)
#define SZ_HW   (VV*DD)
#define OFF_QKV 0
#define OFF_WO  (SZ_QKV)
#define OFF_W1  (OFF_WO + SZ_D2)
#define OFF_W2  (OFF_W1 + SZ_FD)
#define OFF_HW  (OFF_W2 + SZ_FD)
#define WTOT    (OFF_HW + SZ_HW)

// ---------------- device scratch (no allocation allowed) -------------------
__device__ float g_x   [MM*DD];
__device__ float g_qkv [MM*3*DD];
__device__ float g_tmp [MM*DD];
__device__ float g_sc  [(size_t)BB*HH*SS*SS];
__device__ __nv_bfloat16 g_whi[WTOT];
__device__ __nv_bfloat16 g_wlo[WTOT];
__device__ __nv_bfloat16 g_xhi[MM*DD];
__device__ __nv_bfloat16 g_xlo[MM*DD];
__device__ __nv_bfloat16 g_ohi[MM*DD];
__device__ __nv_bfloat16 g_olo[MM*DD];
__device__ __nv_bfloat16 g_fhi[MM*FF];
__device__ __nv_bfloat16 g_flo[MM*FF];

// ---------------- helpers ---------------------------------------------------
__device__ __forceinline__ uint32_t smem_u32(const void* p) {
    uint32_t a;
    asm("{ .reg .u64 t; cvta.to.shared.u64 t, %1; cvt.u32.u64 %0, t; }"
        : "=r"(a) : "l"(p));
    return a;
}
#define LDSM_X4(r0, r1, r2, r3, addr) \
    asm volatile("ldmatrix.sync.aligned.m8n8.x4.shared.b16 {%0,%1,%2,%3}, [%4];" \
                 : "=r"(r0), "=r"(r1), "=r"(r2), "=r"(r3) : "r"(addr))
#define LDSM_X2(r0, r1, addr) \
    asm volatile("ldmatrix.sync.aligned.m8n8.x2.shared.b16 {%0,%1}, [%2];" \
                 : "=r"(r0), "=r"(r1) : "r"(addr))
#define MMA_BF16(c0, c1, c2, c3, a0, a1, a2, a3, b0, b1) \
    asm volatile("mma.sync.aligned.m16n8k16.row.col.f32.bf16.bf16.f32 " \
                 "{%0,%1,%2,%3}, {%4,%5,%6,%7}, {%8,%9}, {%0,%1,%2,%3};" \
                 : "+f"(c0), "+f"(c1), "+f"(c2), "+f"(c3) \
                 : "r"(a0), "r"(a1), "r"(a2), "r"(a3), "r"(b0), "r"(b1))

__device__ __forceinline__ void split1(float v, __nv_bfloat16& h, __nv_bfloat16& l) {
    h = __float2bfloat16(v);
    l = __float2bfloat16(v - __bfloat162float(h));
}

// ---------------- split fp32 -> (hi, lo) bf16 (weights only) ----------------
__global__ void split_bf16(const float* __restrict__ x,
                           __nv_bfloat16* __restrict__ hi,
                           __nv_bfloat16* __restrict__ lo, int n)
{
    int i = (blockIdx.x * 256 + threadIdx.x) * 4;
    if (i >= n) return;
    float4 v = *(const float4*)(x + i);
    __nv_bfloat16 h0, h1, h2, h3, l0, l1, l2, l3;
    split1(v.x, h0, l0); split1(v.y, h1, l1);
    split1(v.z, h2, l2); split1(v.w, h3, l3);
    hi[i + 0] = h0; hi[i + 1] = h1; hi[i + 2] = h2; hi[i + 3] = h3;
    lo[i + 0] = l0; lo[i + 1] = l1; lo[i + 2] = l2; lo[i + 3] = l3;
}

// ---------------- HMMA GEMM: C[M,N] = A[M,K] @ B[N,K]^T ---------------------
// Round-3 proven core: CTA 128x128, 8 warps of 64x32, BK=32, double-buffered
// smem with register staging. 3-pass bf16 split, fp32 accum.
// Epilogue: segmented bias (fused QKV), optional relu, fp32 and/or hi/lo out.
#define SAST 40

__global__ __launch_bounds__(256, 2)
void gemm_mma(const __nv_bfloat16* __restrict__ Ahi, const __nv_bfloat16* __restrict__ Alo,
              const __nv_bfloat16* __restrict__ Bhi, const __nv_bfloat16* __restrict__ Blo,
              const float* __restrict__ bias0, const float* __restrict__ bias1,
              const float* __restrict__ bias2,
              float* __restrict__ C32,
              __nv_bfloat16* __restrict__ Chi, __nv_bfloat16* __restrict__ Clo,
              int M, int N, int K, int relu)
{
    __shared__ __nv_bfloat16 sA[2][128 * SAST];
    __shared__ __nv_bfloat16 sB[2][128 * SAST];

    int tid  = threadIdx.x;
    int lane = tid & 31;
    int wid  = tid >> 5;
    int wm   = (wid & 1) * 64;     // warp M offset
    int wn   = (wid >> 1) * 32;    // warp N offset
    int m0   = blockIdx.y * 128;
    int n0   = blockIdx.x * 128;

    float c[4][4][4];
#pragma unroll
    for (int i = 0; i < 4; i++)
#pragma unroll
        for (int j = 0; j < 4; j++)
#pragma unroll
            for (int r = 0; r < 4; r++) c[i][j][r] = 0.f;

    const int KC = K >> 5;
    const int T  = 3 * KC;

    int srow = tid >> 2, sseg = (tid & 3) * 8;
    int srow2 = (tid + 256) >> 2, sseg2 = ((tid + 256) & 3) * 8;

    uint4 ra0, ra1, rb0, rb1;

    // prologue: chunk 0 (hi*hi)
    ra0 = *(const uint4*)(Ahi + (size_t)(m0 + srow)  * K + sseg);
    ra1 = *(const uint4*)(Ahi + (size_t)(m0 + srow2) * K + sseg2);
    rb0 = *(const uint4*)(Bhi + (size_t)(n0 + srow)  * K + sseg);
    rb1 = *(const uint4*)(Bhi + (size_t)(n0 + srow2) * K + sseg2);
    *(uint4*)&sA[0][srow  * SAST + sseg ] = ra0;
    *(uint4*)&sA[0][srow2 * SAST + sseg2] = ra1;
    *(uint4*)&sB[0][srow  * SAST + sseg ] = rb0;
    *(uint4*)&sB[0][srow2 * SAST + sseg2] = rb1;
    __syncthreads();

    for (int cc = 0; cc < T; ++cc) {
        int p = cc & 1;

        if (cc + 1 < T) {
            int nxt = cc + 1;
            int seg = nxt / KC;
            int k0  = (nxt - seg * KC) << 5;
            const __nv_bfloat16* As = (seg == 2) ? Alo : Ahi;
            const __nv_bfloat16* Bs = (seg == 1) ? Blo : Bhi;
            ra0 = *(const uint4*)(As + (size_t)(m0 + srow)  * K + k0 + sseg);
            ra1 = *(const uint4*)(As + (size_t)(m0 + srow2) * K + k0 + sseg2);
            rb0 = *(const uint4*)(Bs + (size_t)(n0 + srow)  * K + k0 + sseg);
            rb1 = *(const uint4*)(Bs + (size_t)(n0 + srow2) * K + k0 + sseg2);
        }

        uint32_t baseA = smem_u32(&sA[p][0]);
        uint32_t baseB = smem_u32(&sB[p][0]);
#pragma unroll
        for (int kk = 0; kk < 32; kk += 16) {
            uint32_t a[4][4], b[4][2];
#pragma unroll
            for (int ma = 0; ma < 4; ma++) {
                uint32_t addr = baseA +
                    (((wm + ma * 16 + (lane & 15)) * SAST) + kk + ((lane >> 4) * 8)) * 2;
                LDSM_X4(a[ma][0], a[ma][1], a[ma][2], a[ma][3], addr);
            }
#pragma unroll
            for (int nb = 0; nb < 4; nb++) {
                uint32_t addr = baseB +
                    (((wn + nb * 8 + (lane & 7)) * SAST) + kk + (((lane >> 3) & 1) * 8)) * 2;
                LDSM_X2(b[nb][0], b[nb][1], addr);
            }
#pragma unroll
            for (int ma = 0; ma < 4; ma++)
#pragma unroll
                for (int nb = 0; nb < 4; nb++)
                    MMA_BF16(c[ma][nb][0], c[ma][nb][1], c[ma][nb][2], c[ma][nb][3],
                             a[ma][0], a[ma][1], a[ma][2], a[ma][3],
                             b[nb][0], b[nb][1]);
        }

        if (cc + 1 < T) {
            int q = p ^ 1;
            *(uint4*)&sA[q][srow  * SAST + sseg ] = ra0;
            *(uint4*)&sA[q][srow2 * SAST + sseg2] = ra1;
            *(uint4*)&sB[q][srow  * SAST + sseg ] = rb0;
            *(uint4*)&sB[q][srow2 * SAST + sseg2] = rb1;
        }
        __syncthreads();
    }

    // ---- epilogue
#pragma unroll
    for (int ma = 0; ma < 4; ma++) {
        int mrow = m0 + wm + ma * 16 + (lane >> 2);
#pragma unroll
        for (int nb = 0; nb < 4; nb++) {
            int ncol = n0 + wn + nb * 8 + (lane & 3) * 2;
            float b0 = 0.f, b1 = 0.f;
            if (bias0) {
                const float* bb = bias0;
                int off = 0;
                if (bias1 && ncol >= 1024) {
                    if (ncol < 2048) { bb = bias1; off = 1024; }
                    else             { bb = bias2; off = 2048; }
                }
                b0 = bb[ncol - off]; b1 = bb[ncol + 1 - off];
            }
            float v00 = c[ma][nb][0] + b0, v01 = c[ma][nb][1] + b1;
            float v10 = c[ma][nb][2] + b0, v11 = c[ma][nb][3] + b1;
            if (relu) {
                v00 = fmaxf(v00, 0.f); v01 = fmaxf(v01, 0.f);
                v10 = fmaxf(v10, 0.f); v11 = fmaxf(v11, 0.f);
            }
            size_t i0 = (size_t)mrow * N + ncol;
            size_t i1 = (size_t)(mrow + 8) * N + ncol;
            if (C32) {
                *(float2*)(C32 + i0) = make_float2(v00, v01);
                *(float2*)(C32 + i1) = make_float2(v10, v11);
            }
            if (Chi) {
                __nv_bfloat16 h00, h01, h10, h11, l00, l01, l10, l11;
                split1(v00, h00, l00); split1(v01, h01, l01);
                split1(v10, h10, l10); split1(v11, h11, l11);
                *(__nv_bfloat162*)(Chi + i0) = __nv_bfloat162(h00, h01);
                *(__nv_bfloat162*)(Chi + i1) = __nv_bfloat162(h10, h11);
                *(__nv_bfloat162*)(Clo + i0) = __nv_bfloat162(l00, l01);
                *(__nv_bfloat162*)(Clo + i1) = __nv_bfloat162(l10, l11);
            }
        }
    }
}

// ---------------- embedding + PE (emits x + hi/lo) --------------------------
__global__ void embed_pe_kernel(const int* __restrict__ ids,
                                const float* __restrict__ emb,
                                float* __restrict__ x,
                                __nv_bfloat16* __restrict__ xhi,
                                __nv_bfloat16* __restrict__ xlo)
{
    int idx = blockIdx.x * 256 + threadIdx.x;
    int m = idx >> 10;
    int d = idx & 1023;
    int s = m & (SS - 1);
    int tok = ids[m];
    int twohalf = (d >> 1) << 1;
    float div = __expf(-(float)twohalf * (9.210340371976184f / (float)DD));
    float ang = (float)s * div;
    float pe  = (d & 1) ? cosf(ang) : sinf(ang);
    float v = emb[(size_t)tok * DD + d] * 32.0f + pe;
    x[idx] = v;
    __nv_bfloat16 h, l; split1(v, h, l);
    xhi[idx] = h; xlo[idx] = l;
}

// ---------------- attention scores (fp32 SIMT, causal, skip masked) ---------
__global__ __launch_bounds__(256)
void attn_scores(const float* __restrict__ qkv, float* __restrict__ sc)
{
    int bh = blockIdx.z;
    int b = bh >> 4, h = bh & 15;
    int i0 = blockIdx.y * 128, j0 = blockIdx.x * 128;
    if (j0 > i0) return;                       // fully masked tile: skip
    float* out = sc + (size_t)bh * SS * SS;
    int tid = threadIdx.x;

    const float* qb = qkv + (size_t)b * SS * (3 * DD) + h * DKK;
    const float* kb = qb + DD;
    __shared__ float Qs[8][128];
    __shared__ float Ks[8][128];
    int lrow = tid >> 1, lcol = (tid & 1) << 2;
    int ty = tid >> 4, tx = tid & 15;
    float acc[8][8];
#pragma unroll
    for (int i = 0; i < 8; i++)
#pragma unroll
        for (int j = 0; j < 8; j++) acc[i][j] = 0.f;
    for (int k0 = 0; k0 < DKK; k0 += 8) {
        float4 av = *(const float4*)(qb + (size_t)(i0 + lrow) * (3 * DD) + k0 + lcol);
        float4 bv = *(const float4*)(kb + (size_t)(j0 + lrow) * (3 * DD) + k0 + lcol);
        __syncthreads();
        Qs[lcol + 0][lrow] = av.x; Qs[lcol + 1][lrow] = av.y;
        Qs[lcol + 2][lrow] = av.z; Qs[lcol + 3][lrow] = av.w;
        Ks[lcol + 0][lrow] = bv.x; Ks[lcol + 1][lrow] = bv.y;
        Ks[lcol + 2][lrow] = bv.z; Ks[lcol + 3][lrow] = bv.w;
        __syncthreads();
#pragma unroll
        for (int kk = 0; kk < 8; kk++) {
            float a[8], bb_[8];
#pragma unroll
            for (int i = 0; i < 8; i++) a[i]   = Qs[kk][ty * 8 + i];
#pragma unroll
            for (int j = 0; j < 8; j++) bb_[j] = Ks[kk][tx * 8 + j];
#pragma unroll
            for (int i = 0; i < 8; i++)
#pragma unroll
                for (int j = 0; j < 8; j++) acc[i][j] += a[i] * bb_[j];
        }
    }
    const float scale = 0.125f;
#pragma unroll
    for (int i = 0; i < 8; i++) {
        int row = i0 + ty * 8 + i;
#pragma unroll
        for (int j = 0; j < 8; j++) {
            int col = j0 + tx * 8 + j;
            float v = acc[i][j] * scale;
            if (col > row) v = -1e9f;
            out[(size_t)row * SS + col] = v;
        }
    }
}

// ---------------- causal row softmax (valid prefix only) --------------------
__global__ __launch_bounds__(256)
void softmax_rows(float* __restrict__ sc)
{
    int blk = blockIdx.x;
    int i  = blk & (SS - 1);
    int bh = blk >> 10;
    float* p = sc + (size_t)bh * SS * SS + (size_t)i * SS;
    int u = (i >> 8) + 1;
    int t = threadIdx.x, lane = t & 31, w = t >> 5;
    __shared__ float red[8];

    float v[4];
    float m = -3.0e38f;
    for (int s = 0; s < u; s++) {
        int j = t + s * 256;
        float val = (j <= i) ? p[j] : -1e9f;
        v[s] = val;
        m = fmaxf(m, val);
    }
#pragma unroll
    for (int o = 16; o > 0; o >>= 1) m = fmaxf(m, __shfl_xor_sync(~0u, m, o));
    if (lane == 0) red[w] = m;
    __syncthreads();
    m = red[0];
#pragma unroll
    for (int q = 1; q < 8; q++) m = fmaxf(m, red[q]);
    __syncthreads();

    float sum = 0.f;
    for (int s = 0; s < u; s++) { v[s] = __expf(v[s] - m); sum += v[s]; }
#pragma unroll
    for (int o = 16; o > 0; o >>= 1) sum += __shfl_xor_sync(~0u, sum, o);
    if (lane == 0) red[w] = sum;
    __syncthreads();
    sum = red[0];
#pragma unroll
    for (int q = 1; q < 8; q++) sum += red[q];

    float inv = 1.f / sum;
    for (int s = 0; s < u; s++) p[t + s * 256] = v[s] * inv;
}

// ---------------- o = attn @ v (emits hi/lo bf16) ----------------------------
__global__ __launch_bounds__(256)
void attn_av(const float* __restrict__ sc, const float* __restrict__ qkv,
             __nv_bfloat16* __restrict__ ohi, __nv_bfloat16* __restrict__ olo)
{
    int bh = blockIdx.y;
    int b = bh >> 4, h = bh & 15;
    int i0 = blockIdx.x * 64;
    const float* A  = sc  + (size_t)bh * SS * SS;
    const float* vb = qkv + (size_t)b * SS * (3 * DD) + 2 * DD + h * DKK;
    __shared__ float As[16][64];
    __shared__ float Vs[16][64];
    int t  = threadIdx.x;
    int ar = t >> 2,  ac = (t & 3) << 2;
    int vr = t >> 4,  vc = (t & 15) << 2;
    int ty = t >> 4,  tx = t & 15;
    float acc[4][4];
#pragma unroll
    for (int i = 0; i < 4; i++)
#pragma unroll
        for (int j = 0; j < 4; j++) acc[i][j] = 0.f;
    int kmax = i0 + 64;
    for (int k0 = 0; k0 < kmax; k0 += 16) {
        float4 av = *(const float4*)(A  + (size_t)(i0 + ar) * SS + k0 + ac);
        float4 vv = *(const float4*)(vb + (size_t)(k0 + vr) * (3 * DD) + vc);
        __syncthreads();
        As[ac + 0][ar] = av.x; As[ac + 1][ar] = av.y;
        As[ac + 2][ar] = av.z; As[ac + 3][ar] = av.w;
        *(float4*)&Vs[vr][vc] = vv;
        __syncthreads();
#pragma unroll
        for (int kk = 0; kk < 16; kk++) {
            float a[4], bv_[4];
#pragma unroll
            for (int i = 0; i < 4; i++) a[i]   = As[kk][ty * 4 + i];
#pragma unroll
            for (int j = 0; j < 4; j++) bv_[j] = Vs[kk][tx * 4 + j];
#pragma unroll
            for (int i = 0; i < 4; i++)
#pragma unroll
                for (int j = 0; j < 4; j++) acc[i][j] += a[i] * bv_[j];
        }
    }
#pragma unroll
    for (int i = 0; i < 4; i++) {
        size_t row = (size_t)(b * SS + i0 + ty * 4 + i) * DD + h * DKK + tx * 4;
#pragma unroll
        for (int j = 0; j < 4; j += 2) {
            __nv_bfloat16 h0, h1, l0, l1;
            split1(acc[i][j],     h0, l0);
            split1(acc[i][j + 1], h1, l1);
            *(__nv_bfloat162*)(ohi + row + j) = __nv_bfloat162(h0, h1);
            *(__nv_bfloat162*)(olo + row + j) = __nv_bfloat162(l0, l1);
        }
    }
}

// ---------------- fused residual + LayerNorm (emits x + hi/lo) --------------
__global__ __launch_bounds__(256)
void add_ln(const float* __restrict__ x, const float* __restrict__ y,
            const float* __restrict__ g, const float* __restrict__ bta,
            float* __restrict__ out,
            __nv_bfloat16* __restrict__ ohi, __nv_bfloat16* __restrict__ olo)
{
    __shared__ float red[256];
    int row = blockIdx.x;
    int t = threadIdx.x;
    const float* xr = x + (size_t)row * DD;
    float v[4];
    float s = 0.f;
#pragma unroll
    for (int u = 0; u < 4; u++) {
        int idx = t + u * 256;
        float vv = xr[idx];
        if (y) vv += y[(size_t)row * DD + idx];
        v[u] = vv;
        s += vv;
    }
    red[t] = s; __syncthreads();
    for (int w = 128; w > 0; w >>= 1) {
        if (t < w) red[t] += red[t + w];
        __syncthreads();
    }
    float mean = red[0] * (1.f / DD); __syncthreads();
    float s2 = 0.f;
#pragma unroll
    for (int u = 0; u < 4; u++) { float d = v[u] - mean; s2 += d * d; }
    red[t] = s2; __syncthreads();
    for (int w = 128; w > 0; w >>= 1) {
        if (t < w) red[t] += red[t + w];
        __syncthreads();
    }
    float rstd = rsqrtf(red[0] * (1.f / DD) + LNEPS);
    float* orow = out + (size_t)row * DD;
#pragma unroll
    for (int u = 0; u < 4; u++) {
        int idx = t + u * 256;
        float val = (v[u] - mean) * rstd * g[idx] + bta[idx];
        orow[idx] = val;
        __nv_bfloat16 h, l; split1(val, h, l);
        ohi[(size_t)row * DD + idx] = h;
        olo[(size_t)row * DD + idx] = l;
    }
}

// ---------------- host orchestration ----------------------------------------
extern "C" void kernel_launch(void* const* d_in, const int* in_sizes, int n_in,
                              void* d_out, int out_size)
{
    (void)in_sizes; (void)n_in; (void)out_size;
    const int*   ids    = (const int*)  d_in[0];
    const float* embedw = (const float*)d_in[1];
    const float* Wq     = (const float*)d_in[2];
    const float* bq     = (const float*)d_in[3];
    const float* Wk     = (const float*)d_in[4];
    const float* bk     = (const float*)d_in[5];
    const float* Wv     = (const float*)d_in[6];
    const float* bv     = (const float*)d_in[7];
    const float* Wo     = (const float*)d_in[8];
    const float* bo     = (const float*)d_in[9];
    const float* ln1_g  = (const float*)d_in[10];
    const float* ln1_b  = (const float*)d_in[11];
    const float* W1     = (const float*)d_in[12];
    const float* b1     = (const float*)d_in[13];
    const float* W2     = (const float*)d_in[14];
    const float* b2     = (const float*)d_in[15];
    const float* ln2_g  = (const float*)d_in[16];
    const float* ln2_b  = (const float*)d_in[17];
    const float* lnf_g  = (const float*)d_in[18];
    const float* lnf_b  = (const float*)d_in[19];
    const float* head_w = (const float*)d_in[20];
    float* out = (float*)d_out;

    float *x, *qkv, *tmp, *sc;
    __nv_bfloat16 *whi, *wlo, *xhi, *xlo, *ohi, *olo, *fhi, *flo;
    cudaGetSymbolAddress((void**)&x,   g_x);
    cudaGetSymbolAddress((void**)&qkv, g_qkv);
    cudaGetSymbolAddress((void**)&tmp, g_tmp);
    cudaGetSymbolAddress((void**)&sc,  g_sc);
    cudaGetSymbolAddress((void**)&whi, g_whi);
    cudaGetSymbolAddress((void**)&wlo, g_wlo);
    cudaGetSymbolAddress((void**)&xhi, g_xhi);
    cudaGetSymbolAddress((void**)&xlo, g_xlo);
    cudaGetSymbolAddress((void**)&ohi, g_ohi);
    cudaGetSymbolAddress((void**)&olo, g_olo);
    cudaGetSymbolAddress((void**)&fhi, g_fhi);
    cudaGetSymbolAddress((void**)&flo, g_flo);

    auto split = [&](const float* s, __nv_bfloat16* h, __nv_bfloat16* l, int n) {
        split_bf16<<<n / 1024, 256>>>(s, h, l, n);
    };
    auto gemm = [&](const __nv_bfloat16* aH, const __nv_bfloat16* aL,
                    const __nv_bfloat16* bH, const __nv_bfloat16* bL,
                    const float* b0, const float* b1_, const float* b2_,
                    float* C32, __nv_bfloat16* Chi, __nv_bfloat16* Clo,
                    int M, int N, int K, int relu) {
        gemm_mma<<<dim3(N / 128, M / 128), 256>>>(aH, aL, bH, bL, b0, b1_, b2_,
                                                  C32, Chi, Clo, M, N, K, relu);
    };

    // weight split: QKV interleaved per layer, rest contiguous
    for (int l = 0; l < LL; l++) {
        split(Wq + (size_t)l * D2, whi + OFF_QKV + (size_t)(3 * l + 0) * D2,
              wlo + OFF_QKV + (size_t)(3 * l + 0) * D2, D2);
        split(Wk + (size_t)l * D2, whi + OFF_QKV + (size_t)(3 * l + 1) * D2,
              wlo + OFF_QKV + (size_t)(3 * l + 1) * D2, D2);
        split(Wv + (size_t)l * D2, whi + OFF_QKV + (size_t)(3 * l + 2) * D2,
              wlo + OFF_QKV + (size_t)(3 * l + 2) * D2, D2);
    }
    split(Wo,     whi + OFF_WO, wlo + OFF_WO, SZ_D2);
    split(W1,     whi + OFF_W1, wlo + OFF_W1, SZ_FD);
    split(W2,     whi + OFF_W2, wlo + OFF_W2, SZ_FD);
    split(head_w, whi + OFF_HW, wlo + OFF_HW, SZ_HW);

    embed_pe_kernel<<<(MM * DD) / 256, 256>>>(ids, embedw, x, xhi, xlo);

    dim3 gSc(SS / 128, SS / 128, BB * HH);
    dim3 gAv(SS / 64, BB * HH);

    for (int l = 0; l < LL; l++) {
        size_t q3 = OFF_QKV + (size_t)l * 3 * D2;
        size_t od = OFF_WO + (size_t)l * D2;
        size_t f1 = OFF_W1 + (size_t)l * FF * DD;
        size_t f2 = OFF_W2 + (size_t)l * FF * DD;

        // fused QKV: [M, 3072]
        gemm(xhi, xlo, whi + q3, wlo + q3, bq + l * DD, bk + l * DD, bv + l * DD,
             qkv, nullptr, nullptr, MM, 3 * DD, DD, 0);

        attn_scores <<<gSc, 256>>>(qkv, sc);
        softmax_rows<<<BB * HH * SS, 256>>>(sc);
        attn_av     <<<gAv, 256>>>(sc, qkv, ohi, olo);

        gemm(ohi, olo, whi + od, wlo + od, bo + l * DD, nullptr, nullptr,
             tmp, nullptr, nullptr, MM, DD, DD, 0);
        add_ln<<<MM, 256>>>(x, tmp, ln1_g + l * DD, ln1_b + l * DD, x, xhi, xlo);

        gemm(xhi, xlo, whi + f1, wlo + f1, b1 + l * FF, nullptr, nullptr,
             nullptr, fhi, flo, MM, FF, DD, 1);
        gemm(fhi, flo, whi + f2, wlo + f2, b2 + l * DD, nullptr, nullptr,
             tmp, nullptr, nullptr, MM, DD, FF, 0);
        add_ln<<<MM, 256>>>(x, tmp, ln2_g + l * DD, ln2_b + l * DD, x, xhi, xlo);
    }

    add_ln<<<MM, 256>>>(x, (const float*)nullptr, lnf_g, lnf_b, x, xhi, xlo);
    gemm(xhi, xlo, whi + OFF_HW, wlo + OFF_HW, nullptr, nullptr, nullptr,
         out, nullptr, nullptr, MM, VV, DD, 0);
}

// round 6
// speedup vs baseline: 1.9518x; 1.1058x over previous
#include <cuda_runtime.h>
#include <cuda_bf16.h>
#include <math.h>
#include <stdint.h>

// ---------------- problem constants ----------------------------------------
#define BB   2
#define SS   1024
#define DD   1024
#define HH   16
#define DKK  64
#define FF   4096
#define LL   4
#define VV   32000
#define MM   (BB*SS)
#define LNEPS 1e-5f

// ---------------- device scratch (no allocation allowed) -------------------
__device__ float g_x [MM*DD];
__device__ float g_q [MM*DD];
__device__ float g_k [MM*DD];
__device__ float g_v [MM*DD];
__device__ float g_ao[MM*DD];
__device__ float g_y [MM*DD];
__device__ float g_ff[MM*FF];
__device__ float g_sc[(size_t)BB*HH*SS*SS];

// ---------------- helpers ---------------------------------------------------
__device__ __forceinline__ uint32_t smem_u32(const void* p) {
    uint32_t a;
    asm("{ .reg .u64 t; cvta.to.shared.u64 t, %1; cvt.u32.u64 %0, t; }"
        : "=r"(a) : "l"(p));
    return a;
}
#define LDSM_X4(r0, r1, r2, r3, addr) \
    asm volatile("ldmatrix.sync.aligned.m8n8.x4.shared.b16 {%0,%1,%2,%3}, [%4];" \
                 : "=r"(r0), "=r"(r1), "=r"(r2), "=r"(r3) : "r"(addr))
#define LDSM_X2(r0, r1, addr) \
    asm volatile("ldmatrix.sync.aligned.m8n8.x2.shared.b16 {%0,%1}, [%2];" \
                 : "=r"(r0), "=r"(r1) : "r"(addr))
#define MMA_BF16(c0, c1, c2, c3, a0, a1, a2, a3, b0, b1) \
    asm volatile("mma.sync.aligned.m16n8k16.row.col.f32.bf16.bf16.f32 " \
                 "{%0,%1,%2,%3}, {%4,%5,%6,%7}, {%8,%9}, {%0,%1,%2,%3};" \
                 : "+f"(c0), "+f"(c1), "+f"(c2), "+f"(c3) \
                 : "r"(a0), "r"(a1), "r"(a2), "r"(a3), "r"(b0), "r"(b1))

// split float4 -> packed hi-bf16x4 and lo-bf16x4
__device__ __forceinline__ void split4(float4 v, uint2& hi, uint2& lo) {
    uint32_t h0 = (uint32_t)__bfloat16_as_ushort(__float2bfloat16(v.x));
    uint32_t h1 = (uint32_t)__bfloat16_as_ushort(__float2bfloat16(v.y));
    uint32_t h2 = (uint32_t)__bfloat16_as_ushort(__float2bfloat16(v.z));
    uint32_t h3 = (uint32_t)__bfloat16_as_ushort(__float2bfloat16(v.w));
    hi.x = h0 | (h1 << 16);
    hi.y = h2 | (h3 << 16);
    float l0 = v.x - __uint_as_float(h0 << 16);
    float l1 = v.y - __uint_as_float(h1 << 16);
    float l2 = v.z - __uint_as_float(h2 << 16);
    float l3 = v.w - __uint_as_float(h3 << 16);
    uint32_t q0 = (uint32_t)__bfloat16_as_ushort(__float2bfloat16(l0));
    uint32_t q1 = (uint32_t)__bfloat16_as_ushort(__float2bfloat16(l1));
    uint32_t q2 = (uint32_t)__bfloat16_as_ushort(__float2bfloat16(l2));
    uint32_t q3 = (uint32_t)__bfloat16_as_ushort(__float2bfloat16(l3));
    lo.x = q0 | (q1 << 16);
    lo.y = q2 | (q3 << 16);
}

// ---------------- HMMA GEMM on fp32 operands: C = A[M,K] @ B[N,K]^T ---------
// Single K sweep; per BK=32 chunk: split fp32 -> hi/lo bf16 smem, then 3 MMA
// groups (hihi, hilo, lohi). CTA 128x128, 8 warps of 64x32, double buffered.
#define SAST 40
#define TILE_ELEMS (128 * SAST)
#define GSMEM_BYTES (8 * TILE_ELEMS * 2)   // 81920 B

__global__ __launch_bounds__(256)
void gemm_f32(const float* __restrict__ A, const float* __restrict__ B,
              const float* __restrict__ bias, float* __restrict__ C,
              int M, int N, int K, int relu)
{
    extern __shared__ __nv_bfloat16 smem[];
    __nv_bfloat16* tAhi[2] = { smem,                  smem + 4 * TILE_ELEMS };
    __nv_bfloat16* tAlo[2] = { smem + 1 * TILE_ELEMS, smem + 5 * TILE_ELEMS };
    __nv_bfloat16* tBhi[2] = { smem + 2 * TILE_ELEMS, smem + 6 * TILE_ELEMS };
    __nv_bfloat16* tBlo[2] = { smem + 3 * TILE_ELEMS, smem + 7 * TILE_ELEMS };

    int tid  = threadIdx.x;
    int lane = tid & 31;
    int wid  = tid >> 5;
    int wm   = (wid & 1) * 64;
    int wn   = (wid >> 1) * 32;
    int m0   = blockIdx.x * 128;    // M fast-varying: wave shares B tiles in L2
    int n0   = blockIdx.y * 128;

    float c[4][4][4];
#pragma unroll
    for (int i = 0; i < 4; i++)
#pragma unroll
        for (int j = 0; j < 4; j++)
#pragma unroll
            for (int r = 0; r < 4; r++) c[i][j][r] = 0.f;

    const int T = K >> 5;

    int lrow[4], lcol[4];
#pragma unroll
    for (int j = 0; j < 4; j++) {
        int u = tid + j * 256;
        lrow[j] = u >> 3;
        lcol[j] = (u & 7) * 4;
    }

    float4 va[4], vb[4];
#pragma unroll
    for (int j = 0; j < 4; j++) {
        va[j] = *(const float4*)(A + (size_t)(m0 + lrow[j]) * K + lcol[j]);
        vb[j] = *(const float4*)(B + (size_t)(n0 + lrow[j]) * K + lcol[j]);
    }
#pragma unroll
    for (int j = 0; j < 4; j++) {
        uint2 h, l;
        int off = lrow[j] * SAST + lcol[j];
        split4(va[j], h, l);
        *(uint2*)(tAhi[0] + off) = h; *(uint2*)(tAlo[0] + off) = l;
        split4(vb[j], h, l);
        *(uint2*)(tBhi[0] + off) = h; *(uint2*)(tBlo[0] + off) = l;
    }
    __syncthreads();

    for (int cc = 0; cc < T; ++cc) {
        int p = cc & 1;

        if (cc + 1 < T) {
            int k0 = (cc + 1) << 5;
#pragma unroll
            for (int j = 0; j < 4; j++) {
                va[j] = *(const float4*)(A + (size_t)(m0 + lrow[j]) * K + k0 + lcol[j]);
                vb[j] = *(const float4*)(B + (size_t)(n0 + lrow[j]) * K + k0 + lcol[j]);
            }
        }

        uint32_t bAhi = smem_u32(tAhi[p]);
        uint32_t bAlo = smem_u32(tAlo[p]);
        uint32_t bBhi = smem_u32(tBhi[p]);
        uint32_t bBlo = smem_u32(tBlo[p]);
#pragma unroll
        for (int kk = 0; kk < 32; kk += 16) {
            uint32_t ah[4][4], bh[4][2], t0, t1;
            uint32_t aoff = ((wm + (lane & 15)) * SAST + kk + ((lane >> 4) * 8)) * 2;
            uint32_t boff = ((wn + (lane & 7)) * SAST + kk + (((lane >> 3) & 1) * 8)) * 2;
#pragma unroll
            for (int ma = 0; ma < 4; ma++)
                LDSM_X4(ah[ma][0], ah[ma][1], ah[ma][2], ah[ma][3],
                        bAhi + aoff + ma * (16 * SAST * 2));
#pragma unroll
            for (int nb = 0; nb < 4; nb++)
                LDSM_X2(bh[nb][0], bh[nb][1], bBhi + boff + nb * (8 * SAST * 2));
#pragma unroll
            for (int ma = 0; ma < 4; ma++)
#pragma unroll
                for (int nb = 0; nb < 4; nb++)
                    MMA_BF16(c[ma][nb][0], c[ma][nb][1], c[ma][nb][2], c[ma][nb][3],
                             ah[ma][0], ah[ma][1], ah[ma][2], ah[ma][3],
                             bh[nb][0], bh[nb][1]);
#pragma unroll
            for (int nb = 0; nb < 4; nb++) {
                LDSM_X2(t0, t1, bBlo + boff + nb * (8 * SAST * 2));
#pragma unroll
                for (int ma = 0; ma < 4; ma++)
                    MMA_BF16(c[ma][nb][0], c[ma][nb][1], c[ma][nb][2], c[ma][nb][3],
                             ah[ma][0], ah[ma][1], ah[ma][2], ah[ma][3],
                             t0, t1);
            }
#pragma unroll
            for (int ma = 0; ma < 4; ma++) {
                uint32_t al0, al1, al2, al3;
                LDSM_X4(al0, al1, al2, al3, bAlo + aoff + ma * (16 * SAST * 2));
#pragma unroll
                for (int nb = 0; nb < 4; nb++)
                    MMA_BF16(c[ma][nb][0], c[ma][nb][1], c[ma][nb][2], c[ma][nb][3],
                             al0, al1, al2, al3, bh[nb][0], bh[nb][1]);
            }
        }

        if (cc + 1 < T) {
            int q = p ^ 1;
#pragma unroll
            for (int j = 0; j < 4; j++) {
                uint2 h, l;
                int off = lrow[j] * SAST + lcol[j];
                split4(va[j], h, l);
                *(uint2*)(tAhi[q] + off) = h; *(uint2*)(tAlo[q] + off) = l;
                split4(vb[j], h, l);
                *(uint2*)(tBhi[q] + off) = h; *(uint2*)(tBlo[q] + off) = l;
            }
        }
        __syncthreads();
    }

#pragma unroll
    for (int ma = 0; ma < 4; ma++) {
        int mrow = m0 + wm + ma * 16 + (lane >> 2);
#pragma unroll
        for (int nb = 0; nb < 4; nb++) {
            int ncol = n0 + wn + nb * 8 + (lane & 3) * 2;
            float b0 = 0.f, b1 = 0.f;
            if (bias) { b0 = bias[ncol]; b1 = bias[ncol + 1]; }
            float v00 = c[ma][nb][0] + b0, v01 = c[ma][nb][1] + b1;
            float v10 = c[ma][nb][2] + b0, v11 = c[ma][nb][3] + b1;
            if (relu) {
                v00 = fmaxf(v00, 0.f); v01 = fmaxf(v01, 0.f);
                v10 = fmaxf(v10, 0.f); v11 = fmaxf(v11, 0.f);
            }
            *(float2*)(C + (size_t)mrow * N + ncol)       = make_float2(v00, v01);
            *(float2*)(C + (size_t)(mrow + 8) * N + ncol) = make_float2(v10, v11);
        }
    }
}

// ---------------- embedding + sinusoidal PE ---------------------------------
__global__ void embed_pe_kernel(const int* __restrict__ ids,
                                const float* __restrict__ emb,
                                float* __restrict__ x)
{
    int idx = blockIdx.x * 256 + threadIdx.x;
    int m = idx >> 10;
    int d = idx & 1023;
    int s = m & (SS - 1);
    int tok = ids[m];
    int twohalf = (d >> 1) << 1;
    float div = __expf(-(float)twohalf * (9.210340371976184f / (float)DD));
    float ang = (float)s * div;
    float pe  = (d & 1) ? cosf(ang) : sinf(ang);
    x[idx] = emb[(size_t)tok * DD + d] * 32.0f + pe;
}

// ---------------- attention scores (fp32 SIMT, causal, skip masked) ---------
__global__ __launch_bounds__(256)
void attn_scores(const float* __restrict__ q, const float* __restrict__ kmat,
                 float* __restrict__ sc)
{
    int bh = blockIdx.z;
    int b = bh >> 4, h = bh & 15;
    int i0 = blockIdx.y * 128, j0 = blockIdx.x * 128;
    if (j0 > i0) return;
    float* out = sc + (size_t)bh * SS * SS;
    int tid = threadIdx.x;

    const float* qb = q    + (size_t)b * SS * DD + h * DKK;
    const float* kb = kmat + (size_t)b * SS * DD + h * DKK;
    __shared__ float Qs[8][128];
    __shared__ float Ks[8][128];
    int lrow = tid >> 1, lcol = (tid & 1) << 2;
    int ty = tid >> 4, tx = tid & 15;
    float acc[8][8];
#pragma unroll
    for (int i = 0; i < 8; i++)
#pragma unroll
        for (int j = 0; j < 8; j++) acc[i][j] = 0.f;
    for (int k0 = 0; k0 < DKK; k0 += 8) {
        float4 av = *(const float4*)(qb + (size_t)(i0 + lrow) * DD + k0 + lcol);
        float4 bv = *(const float4*)(kb + (size_t)(j0 + lrow) * DD + k0 + lcol);
        __syncthreads();
        Qs[lcol + 0][lrow] = av.x; Qs[lcol + 1][lrow] = av.y;
        Qs[lcol + 2][lrow] = av.z; Qs[lcol + 3][lrow] = av.w;
        Ks[lcol + 0][lrow] = bv.x; Ks[lcol + 1][lrow] = bv.y;
        Ks[lcol + 2][lrow] = bv.z; Ks[lcol + 3][lrow] = bv.w;
        __syncthreads();
#pragma unroll
        for (int kk = 0; kk < 8; kk++) {
            float a[8], bb_[8];
#pragma unroll
            for (int i = 0; i < 8; i++) a[i]   = Qs[kk][ty * 8 + i];
#pragma unroll
            for (int j = 0; j < 8; j++) bb_[j] = Ks[kk][tx * 8 + j];
#pragma unroll
            for (int i = 0; i < 8; i++)
#pragma unroll
                for (int j = 0; j < 8; j++) acc[i][j] += a[i] * bb_[j];
        }
    }
    const float scale = 0.125f;
#pragma unroll
    for (int i = 0; i < 8; i++) {
        int row = i0 + ty * 8 + i;
#pragma unroll
        for (int j = 0; j < 8; j++) {
            int col = j0 + tx * 8 + j;
            float v = acc[i][j] * scale;
            if (col > row) v = -1e9f;
            out[(size_t)row * SS + col] = v;
        }
    }
}

// ---------------- causal row softmax (valid prefix only) --------------------
__global__ __launch_bounds__(256)
void softmax_rows(float* __restrict__ sc)
{
    int blk = blockIdx.x;
    int i  = blk & (SS - 1);
    int bh = blk >> 10;
    float* p = sc + (size_t)bh * SS * SS + (size_t)i * SS;
    int u = (i >> 8) + 1;
    int t = threadIdx.x, lane = t & 31, w = t >> 5;
    __shared__ float red[8];

    float v[4];
    float m = -3.0e38f;
    for (int s = 0; s < u; s++) {
        int j = t + s * 256;
        float val = (j <= i) ? p[j] : -1e9f;
        v[s] = val;
        m = fmaxf(m, val);
    }
#pragma unroll
    for (int o = 16; o > 0; o >>= 1) m = fmaxf(m, __shfl_xor_sync(~0u, m, o));
    if (lane == 0) red[w] = m;
    __syncthreads();
    m = red[0];
#pragma unroll
    for (int q = 1; q < 8; q++) m = fmaxf(m, red[q]);
    __syncthreads();

    float sum = 0.f;
    for (int s = 0; s < u; s++) { v[s] = __expf(v[s] - m); sum += v[s]; }
#pragma unroll
    for (int o = 16; o > 0; o >>= 1) sum += __shfl_xor_sync(~0u, sum, o);
    if (lane == 0) red[w] = sum;
    __syncthreads();
    sum = red[0];
#pragma unroll
    for (int q = 1; q < 8; q++) sum += red[q];

    float inv = 1.f / sum;
    for (int s = 0; s < u; s++) p[t + s * 256] = v[s] * inv;
}

// ---------------- o = attn @ v ------------------------------------------------
__global__ __launch_bounds__(256)
void attn_av(const float* __restrict__ sc, const float* __restrict__ v,
             float* __restrict__ o)
{
    int bh = blockIdx.y;
    int b = bh >> 4, h = bh & 15;
    int i0 = blockIdx.x * 64;
    const float* A  = sc + (size_t)bh * SS * SS;
    const float* vb = v  + (size_t)b * SS * DD + h * DKK;
    __shared__ float As[16][64];
    __shared__ float Vs[16][64];
    int t  = threadIdx.x;
    int ar = t >> 2,  ac = (t & 3) << 2;
    int vr = t >> 4,  vc = (t & 15) << 2;
    int ty = t >> 4,  tx = t & 15;
    float acc[4][4];
#pragma unroll
    for (int i = 0; i < 4; i++)
#pragma unroll
        for (int j = 0; j < 4; j++) acc[i][j] = 0.f;
    int kmax = i0 + 64;
    for (int k0 = 0; k0 < kmax; k0 += 16) {
        float4 av = *(const float4*)(A  + (size_t)(i0 + ar) * SS + k0 + ac);
        float4 vv = *(const float4*)(vb + (size_t)(k0 + vr) * DD + vc);
        __syncthreads();
        As[ac + 0][ar] = av.x; As[ac + 1][ar] = av.y;
        As[ac + 2][ar] = av.z; As[ac + 3][ar] = av.w;
        *(float4*)&Vs[vr][vc] = vv;
        __syncthreads();
#pragma unroll
        for (int kk = 0; kk < 16; kk++) {
            float a[4], bv_[4];
#pragma unroll
            for (int i = 0; i < 4; i++) a[i]   = As[kk][ty * 4 + i];
#pragma unroll
            for (int j = 0; j < 4; j++) bv_[j] = Vs[kk][tx * 4 + j];
#pragma unroll
            for (int i = 0; i < 4; i++)
#pragma unroll
                for (int j = 0; j < 4; j++) acc[i][j] += a[i] * bv_[j];
        }
    }
#pragma unroll
    for (int i = 0; i < 4; i++)
#pragma unroll
        for (int j = 0; j < 4; j++)
            o[(size_t)(b * SS + i0 + ty * 4 + i) * DD + h * DKK + tx * 4 + j]
                = acc[i][j];
}

// ---------------- fused residual + LayerNorm --------------------------------
__global__ __launch_bounds__(256)
void add_ln(const float* __restrict__ x, const float* __restrict__ y,
            const float* __restrict__ g, const float* __restrict__ bta,
            float* __restrict__ out)
{
    __shared__ float red[256];
    int row = blockIdx.x;
    int t = threadIdx.x;
    const float* xr = x + (size_t)row * DD;
    float v[4];
    float s = 0.f;
#pragma unroll
    for (int u = 0; u < 4; u++) {
        int idx = t + u * 256;
        float vv = xr[idx];
        if (y) vv += y[(size_t)row * DD + idx];
        v[u] = vv;
        s += vv;
    }
    red[t] = s; __syncthreads();
    for (int w = 128; w > 0; w >>= 1) {
        if (t < w) red[t] += red[t + w];
        __syncthreads();
    }
    float mean = red[0] * (1.f / DD); __syncthreads();
    float s2 = 0.f;
#pragma unroll
    for (int u = 0; u < 4; u++) { float d = v[u] - mean; s2 += d * d; }
    red[t] = s2; __syncthreads();
    for (int w = 128; w > 0; w >>= 1) {
        if (t < w) red[t] += red[t + w];
        __syncthreads();
    }
    float rstd = rsqrtf(red[0] * (1.f / DD) + LNEPS);
    float* orow = out + (size_t)row * DD;
#pragma unroll
    for (int u = 0; u < 4; u++) {
        int idx = t + u * 256;
        orow[idx] = (v[u] - mean) * rstd * g[idx] + bta[idx];
    }
}

// ---------------- host orchestration ----------------------------------------
extern "C" void kernel_launch(void* const* d_in, const int* in_sizes, int n_in,
                              void* d_out, int out_size)
{
    (void)in_sizes; (void)n_in; (void)out_size;
    const int*   ids    = (const int*)  d_in[0];
    const float* embedw = (const float*)d_in[1];
    const float* Wq     = (const float*)d_in[2];
    const float* bq     = (const float*)d_in[3];
    const float* Wk     = (const float*)d_in[4];
    const float* bk     = (const float*)d_in[5];
    const float* Wv     = (const float*)d_in[6];
    const float* bv     = (const float*)d_in[7];
    const float* Wo     = (const float*)d_in[8];
    const float* bo     = (const float*)d_in[9];
    const float* ln1_g  = (const float*)d_in[10];
    const float* ln1_b  = (const float*)d_in[11];
    const float* W1     = (const float*)d_in[12];
    const float* b1     = (const float*)d_in[13];
    const float* W2     = (const float*)d_in[14];
    const float* b2     = (const float*)d_in[15];
    const float* ln2_g  = (const float*)d_in[16];
    const float* ln2_b  = (const float*)d_in[17];
    const float* lnf_g  = (const float*)d_in[18];
    const float* lnf_b  = (const float*)d_in[19];
    const float* head_w = (const float*)d_in[20];
    float* out = (float*)d_out;

    float *x, *q, *k, *v, *ao, *y, *ff, *sc;
    cudaGetSymbolAddress((void**)&x,  g_x);
    cudaGetSymbolAddress((void**)&q,  g_q);
    cudaGetSymbolAddress((void**)&k,  g_k);
    cudaGetSymbolAddress((void**)&v,  g_v);
    cudaGetSymbolAddress((void**)&ao, g_ao);
    cudaGetSymbolAddress((void**)&y,  g_y);
    cudaGetSymbolAddress((void**)&ff, g_ff);
    cudaGetSymbolAddress((void**)&sc, g_sc);

    cudaFuncSetAttribute(gemm_f32, cudaFuncAttributeMaxDynamicSharedMemorySize,
                         GSMEM_BYTES);

    auto gemm = [&](const float* A, const float* B, const float* bias,
                    float* C, int M, int N, int K, int relu) {
        gemm_f32<<<dim3(M / 128, N / 128), 256, GSMEM_BYTES>>>(
            A, B, bias, C, M, N, K, relu);
    };

    embed_pe_kernel<<<(MM * DD) / 256, 256>>>(ids, embedw, x);

    dim3 gSc(SS / 128, SS / 128, BB * HH);
    dim3 gAv(SS / 64, BB * HH);

    for (int l = 0; l < LL; l++) {
        const float* wq = Wq + (size_t)l * DD * DD;
        const float* wk = Wk + (size_t)l * DD * DD;
        const float* wv = Wv + (size_t)l * DD * DD;
        const float* wo = Wo + (size_t)l * DD * DD;
        const float* w1 = W1 + (size_t)l * FF * DD;
        const float* w2 = W2 + (size_t)l * DD * FF;

        gemm(x, wq, bq + l * DD, q, MM, DD, DD, 0);
        gemm(x, wk, bk + l * DD, k, MM, DD, DD, 0);
        gemm(x, wv, bv + l * DD, v, MM, DD, DD, 0);

        attn_scores <<<gSc, 256>>>(q, k, sc);
        softmax_rows<<<BB * HH * SS, 256>>>(sc);
        attn_av     <<<gAv, 256>>>(sc, v, ao);

        gemm(ao, wo, bo + l * DD, y, MM, DD, DD, 0);
        add_ln<<<MM, 256>>>(x, y, ln1_g + l * DD, ln1_b + l * DD, x);

        gemm(x, w1, b1 + l * FF, ff, MM, FF, DD, 1);
        gemm(ff, w2, b2 + l * DD, y, MM, DD, FF, 0);
        add_ln<<<MM, 256>>>(x, y, ln2_g + l * DD, ln2_b + l * DD, x);
    }

    add_ln<<<MM, 256>>>(x, (const float*)nullptr, lnf_g, lnf_b, x);
    gemm(x, head_w, (const float*)nullptr, out, MM, VV, DD, 0);
}